// round 1
// baseline (speedup 1.0000x reference)
#include <cuda_runtime.h>
#include <cuda_bf16.h>

#define B_SZ   16
#define NUM_CN 25000
#define NUM_VN 50000
#define NUM_E  200000
#define D_EMB  16
#define D_HID  32
#define D_MSG  16

// ---- scratch (device globals; no allocation APIs allowed) ----
// node-partial hidden activations, layout [node][B][32]
__device__ float g_hf_x[(size_t)NUM_CN * B_SZ * D_HID];
__device__ float g_hf_z[(size_t)NUM_CN * B_SZ * D_HID];
__device__ float g_ht_x[(size_t)NUM_VN * B_SZ * D_HID];
__device__ float g_ht_z[(size_t)NUM_VN * B_SZ * D_HID];
// aggregated messages, layout [pol][VN][B][16]
__device__ float g_m[(size_t)2 * NUM_VN * B_SZ * D_MSG];

// ---------------------------------------------------------------------------
// zero the message accumulator
__global__ void __launch_bounds__(256) zero_kernel(float4* p, long n4) {
    long i = (long)blockIdx.x * blockDim.x + threadIdx.x;
    if (i < n4) p[i] = make_float4(0.f, 0.f, 0.f, 0.f);
}

// ---------------------------------------------------------------------------
// node partial: out[n][b][j] = sum_{d<16} h[b][n][d] * W1[rowOff+d][j]   (j<32)
// h layout [B][N][16], W1 row-major [32][32], out layout [N][B][32]
__global__ void __launch_bounds__(256) node_partial_kernel(
    const float* __restrict__ h, const float* __restrict__ W1,
    int rowOff, int N, float* __restrict__ out)
{
    __shared__ float4 Ws[16][8];   // 16 rows x 32 cols
    int t = threadIdx.x;
    if (t < 128) {
        int d = t >> 3, j4 = t & 7;
        Ws[d][j4] = reinterpret_cast<const float4*>(W1 + (size_t)(rowOff + d) * 32)[j4];
    }
    __syncthreads();

    long idx = (long)blockIdx.x * 256 + t;
    if (idx >= (long)N * B_SZ) return;
    int n = (int)(idx >> 4);
    int b = (int)(idx & 15);

    const float4* hp = reinterpret_cast<const float4*>(h + ((size_t)b * N + n) * D_EMB);
    float4 h0 = hp[0], h1 = hp[1], h2 = hp[2], h3 = hp[3];
    float hr[16] = {h0.x,h0.y,h0.z,h0.w, h1.x,h1.y,h1.z,h1.w,
                    h2.x,h2.y,h2.z,h2.w, h3.x,h3.y,h3.z,h3.w};

    float4 acc[8];
    #pragma unroll
    for (int q = 0; q < 8; q++) acc[q] = make_float4(0.f,0.f,0.f,0.f);

    #pragma unroll
    for (int d = 0; d < 16; d++) {
        float hd = hr[d];
        #pragma unroll
        for (int q = 0; q < 8; q++) {
            float4 w = Ws[d][q];
            acc[q].x += hd * w.x; acc[q].y += hd * w.y;
            acc[q].z += hd * w.z; acc[q].w += hd * w.w;
        }
    }

    float4* op = reinterpret_cast<float4*>(out + ((size_t)n * B_SZ + b) * D_HID);
    #pragma unroll
    for (int q = 0; q < 8; q++) op[q] = acc[q];
}

// ---------------------------------------------------------------------------
// edge kernel: hidden = relu(hf[f] + ht[v]); msg = hidden @ W2; m[v] += msg (if syn)
// hf [CN][B][32], ht [VN][B][32], syn [B][CN], W2 [32][16], m [VN][B][16]
__global__ void __launch_bounds__(256) edge_kernel(
    const float* __restrict__ hf, const float* __restrict__ ht,
    const int* __restrict__ from_ind, const int* __restrict__ to_ind,
    const int* __restrict__ syn, const float* __restrict__ W2,
    float* __restrict__ m)
{
    __shared__ float4 W2s[32][4];   // 32 rows x 16 cols
    int t = threadIdx.x;
    if (t < 128) {
        int j = t >> 2, k4 = t & 3;
        W2s[j][k4] = reinterpret_cast<const float4*>(W2 + (size_t)j * 16)[k4];
    }
    __syncthreads();

    long idx = (long)blockIdx.x * 256 + t;
    int e = (int)(idx >> 4);
    int b = (int)(idx & 15);

    int f = __ldg(from_ind + e);
    int v = __ldg(to_ind + e);
    int s = __ldg(syn + (size_t)b * NUM_CN + f);
    if (s == 0) return;   // masked lanes skip all memory traffic

    const float4* ap = reinterpret_cast<const float4*>(hf + ((size_t)f * B_SZ + b) * D_HID);
    const float4* cp = reinterpret_cast<const float4*>(ht + ((size_t)v * B_SZ + b) * D_HID);

    float hid[32];
    #pragma unroll
    for (int q = 0; q < 8; q++) {
        float4 a = ap[q], c = cp[q];
        hid[4*q+0] = fmaxf(a.x + c.x, 0.f);
        hid[4*q+1] = fmaxf(a.y + c.y, 0.f);
        hid[4*q+2] = fmaxf(a.z + c.z, 0.f);
        hid[4*q+3] = fmaxf(a.w + c.w, 0.f);
    }

    float4 msg[4];
    #pragma unroll
    for (int q = 0; q < 4; q++) msg[q] = make_float4(0.f,0.f,0.f,0.f);

    #pragma unroll
    for (int j = 0; j < 32; j++) {
        float hj = hid[j];
        #pragma unroll
        for (int q = 0; q < 4; q++) {
            float4 w = W2s[j][q];
            msg[q].x += hj * w.x; msg[q].y += hj * w.y;
            msg[q].z += hj * w.z; msg[q].w += hj * w.w;
        }
    }

    float* base = m + ((size_t)v * B_SZ + b) * D_MSG;
    #pragma unroll
    for (int q = 0; q < 4; q++) {
        atomicAdd(base + 4*q + 0, msg[q].x);
        atomicAdd(base + 4*q + 1, msg[q].y);
        atomicAdd(base + 4*q + 2, msg[q].z);
        atomicAdd(base + 4*q + 3, msg[q].w);
    }
}

// ---------------------------------------------------------------------------
// vertex MLP: out = relu([m_x|m_z|h_to] @ We1) @ We2
// m [2][VN][B][16], h_to [B][VN][16], We1 [48][32], We2 [32][16], out [B][VN][16]
__global__ void __launch_bounds__(256) vn_kernel(
    const float* __restrict__ m, const float* __restrict__ h_to,
    const float* __restrict__ We1, const float* __restrict__ We2,
    float* __restrict__ out)
{
    __shared__ float4 W1s[48][8];   // 48 x 32
    __shared__ float4 W2s[32][4];   // 32 x 16
    int t = threadIdx.x;
    for (int i = t; i < 384; i += 256) {
        int d = i >> 3, j4 = i & 7;
        W1s[d][j4] = reinterpret_cast<const float4*>(We1 + (size_t)d * 32)[j4];
    }
    if (t < 128) {
        int j = t >> 2, k4 = t & 3;
        W2s[j][k4] = reinterpret_cast<const float4*>(We2 + (size_t)j * 16)[k4];
    }
    __syncthreads();

    int v = blockIdx.x * 256 + t;
    if (v >= NUM_VN) return;
    int b = blockIdx.y;

    float feat[48];
    {
        const float4* px = reinterpret_cast<const float4*>(m + ((size_t)v * B_SZ + b) * D_MSG);
        const float4* pz = reinterpret_cast<const float4*>(m + ((size_t)(NUM_VN + v) * B_SZ + b) * D_MSG);
        const float4* ph = reinterpret_cast<const float4*>(h_to + ((size_t)b * NUM_VN + v) * D_EMB);
        #pragma unroll
        for (int q = 0; q < 4; q++) {
            float4 a = px[q];
            feat[4*q+0]=a.x; feat[4*q+1]=a.y; feat[4*q+2]=a.z; feat[4*q+3]=a.w;
        }
        #pragma unroll
        for (int q = 0; q < 4; q++) {
            float4 a = pz[q];
            feat[16+4*q+0]=a.x; feat[16+4*q+1]=a.y; feat[16+4*q+2]=a.z; feat[16+4*q+3]=a.w;
        }
        #pragma unroll
        for (int q = 0; q < 4; q++) {
            float4 a = ph[q];
            feat[32+4*q+0]=a.x; feat[32+4*q+1]=a.y; feat[32+4*q+2]=a.z; feat[32+4*q+3]=a.w;
        }
    }

    float4 hid4[8];
    #pragma unroll
    for (int q = 0; q < 8; q++) hid4[q] = make_float4(0.f,0.f,0.f,0.f);

    #pragma unroll
    for (int d = 0; d < 48; d++) {
        float fd = feat[d];
        #pragma unroll
        for (int q = 0; q < 8; q++) {
            float4 w = W1s[d][q];
            hid4[q].x += fd * w.x; hid4[q].y += fd * w.y;
            hid4[q].z += fd * w.z; hid4[q].w += fd * w.w;
        }
    }

    float hid[32];
    #pragma unroll
    for (int q = 0; q < 8; q++) {
        hid[4*q+0] = fmaxf(hid4[q].x, 0.f);
        hid[4*q+1] = fmaxf(hid4[q].y, 0.f);
        hid[4*q+2] = fmaxf(hid4[q].z, 0.f);
        hid[4*q+3] = fmaxf(hid4[q].w, 0.f);
    }

    float4 o[4];
    #pragma unroll
    for (int q = 0; q < 4; q++) o[q] = make_float4(0.f,0.f,0.f,0.f);

    #pragma unroll
    for (int j = 0; j < 32; j++) {
        float hj = hid[j];
        #pragma unroll
        for (int q = 0; q < 4; q++) {
            float4 w = W2s[j][q];
            o[q].x += hj * w.x; o[q].y += hj * w.y;
            o[q].z += hj * w.z; o[q].w += hj * w.w;
        }
    }

    float4* op = reinterpret_cast<float4*>(out + ((size_t)b * NUM_VN + v) * D_EMB);
    #pragma unroll
    for (int q = 0; q < 4; q++) op[q] = o[q];
}

// ---------------------------------------------------------------------------
extern "C" void kernel_launch(void* const* d_in, const int* in_sizes, int n_in,
                              void* d_out, int out_size) {
    const float* h_from_x   = (const float*)d_in[0];
    const float* h_from_z   = (const float*)d_in[1];
    const float* h_to       = (const float*)d_in[2];
    const int*   syndrome_x = (const int*)d_in[3];
    const int*   syndrome_z = (const int*)d_in[4];
    const int*   from_ind_x = (const int*)d_in[5];
    const int*   to_ind_x   = (const int*)d_in[6];
    const int*   from_ind_z = (const int*)d_in[7];
    const int*   to_ind_z   = (const int*)d_in[8];
    const float* Wx1        = (const float*)d_in[9];
    const float* Wx2        = (const float*)d_in[10];
    const float* Wz1        = (const float*)d_in[11];
    const float* Wz2        = (const float*)d_in[12];
    const float* We1        = (const float*)d_in[13];
    const float* We2        = (const float*)d_in[14];
    float* out = (float*)d_out;

    float *hf_x, *hf_z, *ht_x, *ht_z, *m;
    cudaGetSymbolAddress((void**)&hf_x, g_hf_x);
    cudaGetSymbolAddress((void**)&hf_z, g_hf_z);
    cudaGetSymbolAddress((void**)&ht_x, g_ht_x);
    cudaGetSymbolAddress((void**)&ht_z, g_ht_z);
    cudaGetSymbolAddress((void**)&m,    g_m);

    // zero message accumulator: 2*VN*B*16 floats = 25.6M -> 6.4M float4
    zero_kernel<<<25000, 256>>>((float4*)m, (long)2 * NUM_VN * B_SZ * D_MSG / 4);

    // node-partial hidden pre-GEMMs
    node_partial_kernel<<<(NUM_CN * B_SZ + 255) / 256, 256>>>(h_from_x, Wx1, 0,  NUM_CN, hf_x);
    node_partial_kernel<<<(NUM_CN * B_SZ + 255) / 256, 256>>>(h_from_z, Wz1, 0,  NUM_CN, hf_z);
    node_partial_kernel<<<(NUM_VN * B_SZ + 255) / 256, 256>>>(h_to,     Wx1, 16, NUM_VN, ht_x);
    node_partial_kernel<<<(NUM_VN * B_SZ + 255) / 256, 256>>>(h_to,     Wz1, 16, NUM_VN, ht_z);

    // edge message + scatter (x then z)
    edge_kernel<<<(NUM_E * B_SZ) / 256, 256>>>(hf_x, ht_x, from_ind_x, to_ind_x,
                                               syndrome_x, Wx2, m);
    edge_kernel<<<(NUM_E * B_SZ) / 256, 256>>>(hf_z, ht_z, from_ind_z, to_ind_z,
                                               syndrome_z, Wz2, m + (size_t)NUM_VN * B_SZ * D_MSG);

    // vertex MLP
    dim3 grid((NUM_VN + 255) / 256, B_SZ);
    vn_kernel<<<grid, 256>>>(m, h_to, We1, We2, out);
}

// round 2
// speedup vs baseline: 1.3139x; 1.3139x over previous
#include <cuda_runtime.h>
#include <cuda_bf16.h>

#define B_SZ   16
#define NUM_CN 25000
#define NUM_VN 50000
#define NUM_E  200000
#define D_EMB  16
#define D_HID  32
#define D_MSG  16

typedef unsigned long long ULL;

// ---- scratch (device globals; no allocation APIs allowed) ----
__device__ float g_hf_x[(size_t)NUM_CN * B_SZ * D_HID];   // [CN][B][32]
__device__ float g_hf_z[(size_t)NUM_CN * B_SZ * D_HID];
__device__ int      g_deg_x[NUM_VN],  g_deg_z[NUM_VN];
__device__ int      g_incl_x[NUM_VN], g_incl_z[NUM_VN];
__device__ int      g_bsum_x[64],     g_bsum_z[64];
__device__ int      g_offs_x[NUM_VN + 1], g_offs_z[NUM_VN + 1];
__device__ int      g_cur_x[NUM_VN],  g_cur_z[NUM_VN];
__device__ int      g_csr_x[NUM_E],   g_csr_z[NUM_E];
__device__ unsigned g_mask_x[NUM_CN], g_mask_z[NUM_CN];

// ---------------------------------------------------------------------------
// f32x2 packed-math helpers (sm_103a)
__device__ __forceinline__ ULL pk2(float x) {
    ULL d; asm("mov.b64 %0, {%1, %1};" : "=l"(d) : "f"(x)); return d;
}
__device__ __forceinline__ float2 up2(ULL a) {
    float lo, hi; asm("mov.b64 {%0, %1}, %2;" : "=f"(lo), "=f"(hi) : "l"(a));
    return make_float2(lo, hi);
}
__device__ __forceinline__ ULL f2fma(ULL a, ULL b, ULL c) {
    ULL d; asm("fma.rn.f32x2 %0, %1, %2, %3;" : "=l"(d) : "l"(a), "l"(b), "l"(c));
    return d;
}

// ---------------------------------------------------------------------------
// histogram of to-indices (both polarities in one launch)
__global__ void __launch_bounds__(256) hist_kernel(
    const int* __restrict__ to_x, const int* __restrict__ to_z,
    int* __restrict__ deg_x, int* __restrict__ deg_z)
{
    int e = blockIdx.x * 256 + threadIdx.x;
    if (e >= NUM_E) return;
    atomicAdd(&deg_x[__ldg(to_x + e)], 1);
    atomicAdd(&deg_z[__ldg(to_z + e)], 1);
}

// block-level inclusive scan (1024-wide Hillis-Steele); blockIdx.y = polarity
__global__ void __launch_bounds__(1024) scan1_kernel(
    const int* __restrict__ deg_x, const int* __restrict__ deg_z,
    int* __restrict__ incl_x, int* __restrict__ incl_z,
    int* __restrict__ bsum_x, int* __restrict__ bsum_z)
{
    const int* deg  = blockIdx.y == 0 ? deg_x  : deg_z;
    int*       incl = blockIdx.y == 0 ? incl_x : incl_z;
    int*       bsum = blockIdx.y == 0 ? bsum_x : bsum_z;
    __shared__ int s[1024];
    int t = threadIdx.x;
    int gid = blockIdx.x * 1024 + t;
    s[t] = (gid < NUM_VN) ? deg[gid] : 0;
    __syncthreads();
    #pragma unroll
    for (int off = 1; off < 1024; off <<= 1) {
        int x = (t >= off) ? s[t - off] : 0;
        __syncthreads();
        s[t] += x;
        __syncthreads();
    }
    if (gid < NUM_VN) incl[gid] = s[t];
    if (t == 1023) bsum[blockIdx.x] = s[t];
}

// scan of block sums; blockIdx.x = polarity
__global__ void __launch_bounds__(64) scan2_kernel(int* bsum_x, int* bsum_z, int nb)
{
    int* bs = blockIdx.x == 0 ? bsum_x : bsum_z;
    __shared__ int s[64];
    int t = threadIdx.x;
    s[t] = (t < nb) ? bs[t] : 0;
    __syncthreads();
    #pragma unroll
    for (int off = 1; off < 64; off <<= 1) {
        int x = (t >= off) ? s[t - off] : 0;
        __syncthreads();
        s[t] += x;
        __syncthreads();
    }
    if (t < nb) bs[t] = s[t];
}

// produce exclusive offsets; blockIdx.y = polarity
__global__ void __launch_bounds__(1024) scan3_kernel(
    const int* __restrict__ incl_x, const int* __restrict__ incl_z,
    const int* __restrict__ bsum_x, const int* __restrict__ bsum_z,
    int* __restrict__ offs_x, int* __restrict__ offs_z)
{
    const int* incl = blockIdx.y == 0 ? incl_x : incl_z;
    const int* bsum = blockIdx.y == 0 ? bsum_x : bsum_z;
    int*       offs = blockIdx.y == 0 ? offs_x : offs_z;
    int gid = blockIdx.x * 1024 + threadIdx.x;
    if (gid < NUM_VN) {
        int add = (blockIdx.x > 0) ? bsum[blockIdx.x - 1] : 0;
        offs[gid + 1] = incl[gid] + add;
    }
    if (gid == 0) offs[0] = 0;
}

// fill CSR payload (from-index per sorted edge slot)
__global__ void __launch_bounds__(256) fill_kernel(
    const int* __restrict__ from_x, const int* __restrict__ to_x,
    const int* __restrict__ from_z, const int* __restrict__ to_z,
    const int* __restrict__ offs_x, const int* __restrict__ offs_z,
    int* __restrict__ cur_x, int* __restrict__ cur_z,
    int* __restrict__ csr_x, int* __restrict__ csr_z)
{
    int e = blockIdx.x * 256 + threadIdx.x;
    if (e >= NUM_E) return;
    {
        int v = __ldg(to_x + e);
        int p = atomicAdd(&cur_x[v], 1);
        csr_x[__ldg(offs_x + v) + p] = __ldg(from_x + e);
    }
    {
        int v = __ldg(to_z + e);
        int p = atomicAdd(&cur_z[v], 1);
        csr_z[__ldg(offs_z + v) + p] = __ldg(from_z + e);
    }
}

// pack syndromes into per-CN 16-bit masks; blockIdx.y = polarity
__global__ void __launch_bounds__(256) mask_kernel(
    const int* __restrict__ syn_x, const int* __restrict__ syn_z,
    unsigned* __restrict__ mask_x, unsigned* __restrict__ mask_z)
{
    const int* syn  = blockIdx.y == 0 ? syn_x  : syn_z;
    unsigned*  mask = blockIdx.y == 0 ? mask_x : mask_z;
    int f = blockIdx.x * 256 + threadIdx.x;
    if (f >= NUM_CN) return;
    unsigned m = 0;
    #pragma unroll
    for (int b = 0; b < B_SZ; b++)
        m |= (unsigned)(__ldg(syn + (size_t)b * NUM_CN + f) & 1) << b;
    mask[f] = m;
}

// ---------------------------------------------------------------------------
// CN partial: out[n][b][j] = sum_{d<16} h[b][n][d] * W1[d][j]  (j<32)
__global__ void __launch_bounds__(256) node_partial_kernel(
    const float* __restrict__ h, const float* __restrict__ W1,
    int N, float* __restrict__ out)
{
    __shared__ ULL Ws[16][16];   // 16 rows x 32 cols (packed pairs)
    int t = threadIdx.x;
    if (t < 256) {
        // 256 packed pairs total
        Ws[t >> 4][t & 15] = reinterpret_cast<const ULL*>(W1)[t];
    }
    __syncthreads();

    long idx = (long)blockIdx.x * 256 + t;
    if (idx >= (long)N * B_SZ) return;
    int n = (int)(idx >> 4);
    int b = (int)(idx & 15);

    const float4* hp = reinterpret_cast<const float4*>(h + ((size_t)b * N + n) * D_EMB);
    float4 h0 = hp[0], h1 = hp[1], h2 = hp[2], h3 = hp[3];
    float hr[16] = {h0.x,h0.y,h0.z,h0.w, h1.x,h1.y,h1.z,h1.w,
                    h2.x,h2.y,h2.z,h2.w, h3.x,h3.y,h3.z,h3.w};

    ULL acc[16];
    #pragma unroll
    for (int q = 0; q < 16; q++) acc[q] = 0ull;

    #pragma unroll
    for (int d = 0; d < 16; d++) {
        ULL hd = pk2(hr[d]);
        #pragma unroll
        for (int q = 0; q < 16; q++) acc[q] = f2fma(hd, Ws[d][q], acc[q]);
    }

    ULL* op = reinterpret_cast<ULL*>(out + ((size_t)n * B_SZ + b) * D_HID);
    #pragma unroll
    for (int q = 0; q < 16; q++) op[q] = acc[q];
}

// ---------------------------------------------------------------------------
// fused: per (v,b) — inline h_to partial, walk CSR edges, msg GEMM, segment sum
// in registers, then vertex MLP. No atomics, no message scratch.
__device__ __forceinline__ void edge_accum(
    int v, int b,
    const int* __restrict__ offs, const int* __restrict__ csr,
    const unsigned* __restrict__ msk, const float* __restrict__ hf,
    const ULL* sW2, const ULL* hp, ULL* m)
{
    int beg = __ldg(offs + v), end = __ldg(offs + v + 1);
    for (int e = beg; e < end; e++) {
        int f = __ldg(csr + e);
        unsigned mk = __ldg(msk + f);
        if ((mk >> b) & 1u) {
            const float4* ap = reinterpret_cast<const float4*>(
                hf + ((size_t)f * B_SZ + b) * D_HID);
            float hid[32];
            #pragma unroll
            for (int q = 0; q < 8; q++) {
                float4 a = ap[q];
                float2 p0 = up2(hp[2*q]), p1 = up2(hp[2*q+1]);
                hid[4*q+0] = fmaxf(a.x + p0.x, 0.f);
                hid[4*q+1] = fmaxf(a.y + p0.y, 0.f);
                hid[4*q+2] = fmaxf(a.z + p1.x, 0.f);
                hid[4*q+3] = fmaxf(a.w + p1.y, 0.f);
            }
            #pragma unroll
            for (int j = 0; j < 32; j++) {
                ULL hj = pk2(hid[j]);
                #pragma unroll
                for (int q = 0; q < 8; q++)
                    m[q] = f2fma(hj, sW2[j*8 + q], m[q]);
            }
        }
    }
}

__global__ void __launch_bounds__(128) fused_vn_kernel(
    const float* __restrict__ h_to,
    const float* __restrict__ hfx, const float* __restrict__ hfz,
    const int* __restrict__ offs_x, const int* __restrict__ csr_x,
    const int* __restrict__ offs_z, const int* __restrict__ csr_z,
    const unsigned* __restrict__ mask_x, const unsigned* __restrict__ mask_z,
    const float* __restrict__ Wx1, const float* __restrict__ Wz1,
    const float* __restrict__ Wx2, const float* __restrict__ Wz2,
    const float* __restrict__ We1, const float* __restrict__ We2,
    float* __restrict__ out)
{
    // packed weight cache:
    // [0,256)    Wx1 rows 16..31 (16x32)     [256,512)  Wz1 rows 16..31
    // [512,768)  Wx2 (32x16)                 [768,1024) Wz2
    // [1024,1792) We1 (48x32)                [1792,2048) We2 (32x16)
    __shared__ ULL sW[2048];
    int t = threadIdx.x;
    {
        const ULL* wx1h = reinterpret_cast<const ULL*>(Wx1 + 16 * 32);
        const ULL* wz1h = reinterpret_cast<const ULL*>(Wz1 + 16 * 32);
        const ULL* wx2  = reinterpret_cast<const ULL*>(Wx2);
        const ULL* wz2  = reinterpret_cast<const ULL*>(Wz2);
        const ULL* we1  = reinterpret_cast<const ULL*>(We1);
        const ULL* we2  = reinterpret_cast<const ULL*>(We2);
        for (int i = t; i < 256; i += 128) sW[i]        = wx1h[i];
        for (int i = t; i < 256; i += 128) sW[256 + i]  = wz1h[i];
        for (int i = t; i < 256; i += 128) sW[512 + i]  = wx2[i];
        for (int i = t; i < 256; i += 128) sW[768 + i]  = wz2[i];
        for (int i = t; i < 768; i += 128) sW[1024 + i] = we1[i];
        for (int i = t; i < 256; i += 128) sW[1792 + i] = we2[i];
    }
    __syncthreads();

    long idx = (long)blockIdx.x * 128 + t;     // grid covers exactly VN*B
    int v = (int)(idx >> 4);
    int b = (int)(idx & 15);

    // load h_to[b][v][:]
    float htv[16];
    {
        const float4* ph = reinterpret_cast<const float4*>(
            h_to + ((size_t)b * NUM_VN + v) * D_EMB);
        #pragma unroll
        for (int q = 0; q < 4; q++) {
            float4 a = ph[q];
            htv[4*q+0]=a.x; htv[4*q+1]=a.y; htv[4*q+2]=a.z; htv[4*q+3]=a.w;
        }
    }

    ULL hp[16], mx[8], mz[8];

    // ---- X polarity ----
    #pragma unroll
    for (int q = 0; q < 16; q++) hp[q] = 0ull;
    #pragma unroll
    for (int d = 0; d < 16; d++) {
        ULL hd = pk2(htv[d]);
        #pragma unroll
        for (int q = 0; q < 16; q++) hp[q] = f2fma(hd, sW[d*16 + q], hp[q]);
    }
    #pragma unroll
    for (int q = 0; q < 8; q++) mx[q] = 0ull;
    edge_accum(v, b, offs_x, csr_x, mask_x, hfx, sW + 512, hp, mx);

    // ---- Z polarity ----
    #pragma unroll
    for (int q = 0; q < 16; q++) hp[q] = 0ull;
    #pragma unroll
    for (int d = 0; d < 16; d++) {
        ULL hd = pk2(htv[d]);
        #pragma unroll
        for (int q = 0; q < 16; q++) hp[q] = f2fma(hd, sW[256 + d*16 + q], hp[q]);
    }
    #pragma unroll
    for (int q = 0; q < 8; q++) mz[q] = 0ull;
    edge_accum(v, b, offs_z, csr_z, mask_z, hfz, sW + 768, hp, mz);

    // ---- vertex MLP: feat = [mx | mz | htv] @ We1, relu, @ We2 ----
    ULL acc[16];
    #pragma unroll
    for (int q = 0; q < 16; q++) acc[q] = 0ull;

    #pragma unroll
    for (int dp = 0; dp < 8; dp++) {
        float2 p = up2(mx[dp]);
        ULL f0 = pk2(p.x), f1 = pk2(p.y);
        const ULL* r0 = &sW[1024 + (2*dp) * 16];
        #pragma unroll
        for (int q = 0; q < 16; q++) acc[q] = f2fma(f0, r0[q],      acc[q]);
        #pragma unroll
        for (int q = 0; q < 16; q++) acc[q] = f2fma(f1, r0[16 + q], acc[q]);
    }
    #pragma unroll
    for (int dp = 0; dp < 8; dp++) {
        float2 p = up2(mz[dp]);
        ULL f0 = pk2(p.x), f1 = pk2(p.y);
        const ULL* r0 = &sW[1024 + (16 + 2*dp) * 16];
        #pragma unroll
        for (int q = 0; q < 16; q++) acc[q] = f2fma(f0, r0[q],      acc[q]);
        #pragma unroll
        for (int q = 0; q < 16; q++) acc[q] = f2fma(f1, r0[16 + q], acc[q]);
    }
    #pragma unroll
    for (int d = 0; d < 16; d++) {
        ULL fd = pk2(htv[d]);
        const ULL* r = &sW[1024 + (32 + d) * 16];
        #pragma unroll
        for (int q = 0; q < 16; q++) acc[q] = f2fma(fd, r[q], acc[q]);
    }

    float hid[32];
    #pragma unroll
    for (int q = 0; q < 16; q++) {
        float2 p = up2(acc[q]);
        hid[2*q+0] = fmaxf(p.x, 0.f);
        hid[2*q+1] = fmaxf(p.y, 0.f);
    }

    ULL o[8];
    #pragma unroll
    for (int q = 0; q < 8; q++) o[q] = 0ull;
    #pragma unroll
    for (int j = 0; j < 32; j++) {
        ULL hj = pk2(hid[j]);
        #pragma unroll
        for (int q = 0; q < 8; q++) o[q] = f2fma(hj, sW[1792 + j*8 + q], o[q]);
    }

    ULL* op = reinterpret_cast<ULL*>(out + ((size_t)b * NUM_VN + v) * D_EMB);
    #pragma unroll
    for (int q = 0; q < 8; q++) op[q] = o[q];
}

// ---------------------------------------------------------------------------
extern "C" void kernel_launch(void* const* d_in, const int* in_sizes, int n_in,
                              void* d_out, int out_size) {
    const float* h_from_x   = (const float*)d_in[0];
    const float* h_from_z   = (const float*)d_in[1];
    const float* h_to       = (const float*)d_in[2];
    const int*   syndrome_x = (const int*)d_in[3];
    const int*   syndrome_z = (const int*)d_in[4];
    const int*   from_ind_x = (const int*)d_in[5];
    const int*   to_ind_x   = (const int*)d_in[6];
    const int*   from_ind_z = (const int*)d_in[7];
    const int*   to_ind_z   = (const int*)d_in[8];
    const float* Wx1        = (const float*)d_in[9];
    const float* Wx2        = (const float*)d_in[10];
    const float* Wz1        = (const float*)d_in[11];
    const float* Wz2        = (const float*)d_in[12];
    const float* We1        = (const float*)d_in[13];
    const float* We2        = (const float*)d_in[14];
    float* out = (float*)d_out;

    float *hf_x, *hf_z;
    int *deg_x, *deg_z, *incl_x, *incl_z, *bsum_x, *bsum_z;
    int *offs_x, *offs_z, *cur_x, *cur_z, *csr_x, *csr_z;
    unsigned *mask_x, *mask_z;
    cudaGetSymbolAddress((void**)&hf_x, g_hf_x);
    cudaGetSymbolAddress((void**)&hf_z, g_hf_z);
    cudaGetSymbolAddress((void**)&deg_x, g_deg_x);
    cudaGetSymbolAddress((void**)&deg_z, g_deg_z);
    cudaGetSymbolAddress((void**)&incl_x, g_incl_x);
    cudaGetSymbolAddress((void**)&incl_z, g_incl_z);
    cudaGetSymbolAddress((void**)&bsum_x, g_bsum_x);
    cudaGetSymbolAddress((void**)&bsum_z, g_bsum_z);
    cudaGetSymbolAddress((void**)&offs_x, g_offs_x);
    cudaGetSymbolAddress((void**)&offs_z, g_offs_z);
    cudaGetSymbolAddress((void**)&cur_x, g_cur_x);
    cudaGetSymbolAddress((void**)&cur_z, g_cur_z);
    cudaGetSymbolAddress((void**)&csr_x, g_csr_x);
    cudaGetSymbolAddress((void**)&csr_z, g_csr_z);
    cudaGetSymbolAddress((void**)&mask_x, g_mask_x);
    cudaGetSymbolAddress((void**)&mask_z, g_mask_z);

    // reset degree/cursor counters
    cudaMemsetAsync(deg_x, 0, NUM_VN * sizeof(int), 0);
    cudaMemsetAsync(deg_z, 0, NUM_VN * sizeof(int), 0);
    cudaMemsetAsync(cur_x, 0, NUM_VN * sizeof(int), 0);
    cudaMemsetAsync(cur_z, 0, NUM_VN * sizeof(int), 0);

    const int EB = (NUM_E + 255) / 256;
    const int SB = (NUM_VN + 1023) / 1024;     // 49

    // CSR build
    hist_kernel<<<EB, 256>>>(to_ind_x, to_ind_z, deg_x, deg_z);
    scan1_kernel<<<dim3(SB, 2), 1024>>>(deg_x, deg_z, incl_x, incl_z, bsum_x, bsum_z);
    scan2_kernel<<<2, 64>>>(bsum_x, bsum_z, SB);
    scan3_kernel<<<dim3(SB, 2), 1024>>>(incl_x, incl_z, bsum_x, bsum_z, offs_x, offs_z);
    fill_kernel<<<EB, 256>>>(from_ind_x, to_ind_x, from_ind_z, to_ind_z,
                             offs_x, offs_z, cur_x, cur_z, csr_x, csr_z);

    // syndrome bitmasks
    mask_kernel<<<dim3((NUM_CN + 255) / 256, 2), 256>>>(syndrome_x, syndrome_z,
                                                        mask_x, mask_z);

    // CN-side hidden partials
    node_partial_kernel<<<(NUM_CN * B_SZ + 255) / 256, 256>>>(h_from_x, Wx1, NUM_CN, hf_x);
    node_partial_kernel<<<(NUM_CN * B_SZ + 255) / 256, 256>>>(h_from_z, Wz1, NUM_CN, hf_z);

    // fused edge + reduce + vertex MLP
    fused_vn_kernel<<<(NUM_VN * B_SZ) / 128, 128>>>(
        h_to, hf_x, hf_z,
        offs_x, csr_x, offs_z, csr_z, mask_x, mask_z,
        Wx1, Wz1, Wx2, Wz2, We1, We2, out);
}